// round 13
// baseline (speedup 1.0000x reference)
#include <cuda_runtime.h>
#include <cuda_fp16.h>
#include <math.h>
#include <stdint.h>

#define T_ 70
#define B_ 64
#define NTOK 33278
#define NINP_ 400
#define NHID_ 1150
#define DP 1152                 // padded hidden stride (halves)
#define KP0H 448                // padded 400-dim (halves)
#define M_ (T_*B_)              // 4480
#define GSW 36                  // persist smem row words (32 + 4 pad)
#define SRW 32                  // gemm swizzled row words
#define STG3 (2*128*SRW)        // gemm stage words (8192)
#define DECROWS 33536           // 262*128
#define PB0 2016                // pack_b layer0 blocks (4608*448/4/256)
#define PW0 5184                // pack_wh blocks (4*DP*DP/4/256)
#define HCB 288                 // init blocks (B_*DP/256)

// ---------------- static scratch ------------------------------------------
__device__ __half g_x0   [M_*KP0H];
__device__ float  g_xpre0[M_*4*NHID_];
__device__ float  g_xpre1[M_*4*NHID_];
__device__ float  g_xpre2[M_*4*NINP_];
__device__ __half g_hs0  [M_*DP];
__device__ __half g_hs1  [M_*DP];
__device__ __half g_hs2  [M_*KP0H];
__device__ __half g_h    [2][B_*DP];
__device__ __half g_whp  [4*DP*DP];
__device__ __half g_wip  [4608*DP];
__device__ __half g_dec  [DECROWS*KP0H];
__device__ unsigned int g_ctr;

// ---------------- helpers -------------------------------------------------
__device__ __forceinline__ void mma16(float* c, const uint32_t* a, const uint32_t* b){
    asm volatile("mma.sync.aligned.m16n8k16.row.col.f32.f16.f16.f32 "
        "{%0,%1,%2,%3},{%4,%5,%6,%7},{%8,%9},{%0,%1,%2,%3};"
        : "+f"(c[0]),"+f"(c[1]),"+f"(c[2]),"+f"(c[3])
        : "r"(a[0]),"r"(a[1]),"r"(a[2]),"r"(a[3]),"r"(b[0]),"r"(b[1]));
}
__device__ __forceinline__ void cpa16(void* smem, const void* gmem){
    uint32_t s = (uint32_t)__cvta_generic_to_shared(smem);
    asm volatile("cp.async.cg.shared.global [%0], [%1], 16;" :: "r"(s), "l"(gmem));
}
__device__ __forceinline__ void cpcommit(){ asm volatile("cp.async.commit_group;"); }
template<int N> __device__ __forceinline__ void cpwait(){ asm volatile("cp.async.wait_group %0;" :: "n"(N)); }

// ---------------- fused: embed + pack_b (layer0) ----------------------------
__global__ void embed_packb0(const int* __restrict__ inp, const float* __restrict__ emb_w,
                             const float* __restrict__ wi0) {
    if (blockIdx.x < M_) {
        int token = blockIdx.x;
        int tok   = inp[token];
        const float* src = emb_w + (size_t)tok * NINP_;
        __half* dst = g_x0 + (size_t)token * KP0H;
        int j = threadIdx.x * 4;
        if (j < KP0H) {
            __half v[4];
            #pragma unroll
            for (int x = 0; x < 4; ++x) v[x] = (j + x < NINP_) ? __float2half_rn(src[j + x]) : __half(0.f);
            *(uint2*)(dst + j) = *(uint2*)v;
        }
    } else {
        long idx = (long)(blockIdx.x - M_) * 256 + threadIdx.x;
        long total4 = (long)4608 * KP0H / 4;
        if (idx >= total4) return;
        int kq = (int)(idx % (KP0H >> 2)) << 2;
        long n = idx / (KP0H >> 2);
        __half v[4];
        #pragma unroll
        for (int x = 0; x < 4; ++x)
            v[x] = (n < 4*NHID_ && kq + x < NINP_) ? __float2half_rn(wi0[n*NINP_ + kq + x]) : __half(0.f);
        *(uint2*)(g_wip + n*KP0H + kq) = *(uint2*)v;
    }
}

// ---------------- fused: pack_wh + init_hc (layer0) -------------------------
__global__ void packwh_init0(const float* __restrict__ wh, const float* __restrict__ h0, int D) {
    if (blockIdx.x < PW0) {
        long idx = (long)blockIdx.x * 256 + threadIdx.x;
        int kq = (int)(idx % (DP >> 2)) << 2;
        long r = idx / (DP >> 2);
        int u = (int)(r % DP);
        int gate = (int)(r / DP);
        __half v[4];
        #pragma unroll
        for (int x = 0; x < 4; ++x)
            v[x] = (u < D && kq + x < D) ? __float2half_rn(wh[((size_t)(gate*D + u))*D + kq + x]) : __half(0.f);
        *(uint2*)(g_whp + r*DP + kq) = *(uint2*)v;
    } else {
        int i = (blockIdx.x - PW0) * 256 + threadIdx.x;
        if (i == 0) g_ctr = 0;
        if (i >= B_*DP) return;
        int b = i / DP, u = i - b*DP;
        g_h[0][i] = (u < D) ? __float2half_rn(h0[b*D + u]) : __half(0.f);
    }
}

// ---------------- pack kernels (layers 1/2, decoder) ------------------------
__global__ void pack_b(const float* __restrict__ src, __half* __restrict__ dst,
                       int N, int K, int KP, long total4) {
    long idx = (long)blockIdx.x * 256 + threadIdx.x;
    if (idx >= total4) return;
    int kq = (int)(idx % (KP >> 2)) << 2;
    long n = idx / (KP >> 2);
    __half v[4];
    #pragma unroll
    for (int x = 0; x < 4; ++x)
        v[x] = (n < N && kq + x < K) ? __float2half_rn(src[n*K + kq + x]) : __half(0.f);
    *(uint2*)(dst + n*KP + kq) = *(uint2*)v;
}

__global__ void pack_wh(const float* __restrict__ wh, int D, int Kp, long total4) {
    long idx = (long)blockIdx.x * 256 + threadIdx.x;
    if (idx >= total4) return;
    int kq = (int)(idx % (Kp >> 2)) << 2;
    long r = idx / (Kp >> 2);
    int u = (int)(r % DP);
    int gate = (int)(r / DP);
    __half v[4];
    #pragma unroll
    for (int x = 0; x < 4; ++x)
        v[x] = (u < D && kq + x < D) ? __float2half_rn(wh[((size_t)(gate*D + u))*D + kq + x]) : __half(0.f);
    *(uint2*)(g_whp + r*Kp + kq) = *(uint2*)v;
}

__global__ void init_hc(const float* __restrict__ h0, int D) {
    int i = blockIdx.x * 256 + threadIdx.x;
    if (i == 0) g_ctr = 0;
    if (i >= B_*DP) return;
    int b = i / DP, u = i - b*DP;
    g_h[0][i] = (u < D) ? __float2half_rn(h0[b*D + u]) : __half(0.f);
}

// ---------------- fp16 GEMM (unchanged from R12) ----------------------------
__global__ __launch_bounds__(128, 2) void gemm_mma(
    const __half* __restrict__ A, int lda,
    const __half* __restrict__ B, int ldb,
    const float* __restrict__ bias, float* __restrict__ C,
    int N, int KT)
{
    extern __shared__ uint32_t sm[];
    int tid = threadIdx.x, wid = tid >> 5, lane = tid & 31;
    int g = lane >> 2, tg = lane & 3;
    int wm = wid >> 1, wn = wid & 1;
    int m0 = blockIdx.y * 128, n0 = blockIdx.x * 128;
    int r0 = tid >> 3, q = tid & 7;
    int swz = ((q ^ (r0 & 7)) << 2);

    float acc[4][8][4];
    #pragma unroll
    for (int i = 0; i < 4; ++i)
        #pragma unroll
        for (int j = 0; j < 8; ++j)
            #pragma unroll
            for (int r = 0; r < 4; ++r) acc[i][j][r] = 0.f;

    auto load_tile = [&](int s, int k0) {
        uint32_t* st = sm + s*STG3;
        const __half* ag = A + (size_t)(m0 + r0)*lda + k0 + q*8;
        #pragma unroll
        for (int it = 0; it < 8; ++it)
            cpa16(&st[(r0 + it*16)*SRW + swz], ag + (size_t)it*16*lda);
        uint32_t* sb = st + 128*SRW;
        const __half* bg = B + (size_t)(n0 + r0)*ldb + k0 + q*8;
        #pragma unroll
        for (int it = 0; it < 8; ++it)
            cpa16(&sb[(r0 + it*16)*SRW + swz], bg + (size_t)it*16*ldb);
    };

    load_tile(0, 0);  cpcommit();
    load_tile(1, 64); cpcommit();

    uint32_t a[2][4][4], b[2][8][2];

    for (int kt = 0; kt < KT; ++kt) {
        cpwait<1>();
        __syncthreads();
        if (kt + 2 < KT) load_tile((kt + 2) % 3, (kt + 2)*64);
        cpcommit();

        const uint32_t* Ast = sm + (kt % 3)*STG3;
        const uint32_t* Bst = Ast + 128*SRW;

        auto ldfrag = [&](int buf, int ka) {
            int aw0 = (((ka*2)     ^ g) << 2) + tg;
            int aw1 = (((ka*2 + 1) ^ g) << 2) + tg;
            #pragma unroll
            for (int i = 0; i < 4; ++i) {
                int mr = wm*64 + i*16 + g;
                a[buf][i][0] = Ast[mr*SRW + aw0];
                a[buf][i][1] = Ast[(mr+8)*SRW + aw0];
                a[buf][i][2] = Ast[mr*SRW + aw1];
                a[buf][i][3] = Ast[(mr+8)*SRW + aw1];
            }
            #pragma unroll
            for (int j = 0; j < 8; ++j) {
                int nc = wn*64 + j*8 + g;
                b[buf][j][0] = Bst[nc*SRW + aw0];
                b[buf][j][1] = Bst[nc*SRW + aw1];
            }
        };

        ldfrag(0, 0);
        #pragma unroll
        for (int ka = 0; ka < 4; ++ka) {
            int cur = ka & 1;
            if (ka < 3) ldfrag(cur ^ 1, ka + 1);
            #pragma unroll
            for (int i = 0; i < 4; ++i)
                #pragma unroll
                for (int j = 0; j < 8; ++j) mma16(acc[i][j], a[cur][i], b[cur][j]);
        }
    }

    #pragma unroll
    for (int i = 0; i < 4; ++i) {
        #pragma unroll
        for (int j = 0; j < 8; ++j) {
            int row0 = m0 + wm*64 + i*16 + g;
            int col0 = n0 + wn*64 + j*8 + tg*2;
            if (col0 < N) {
                float b0 = bias[col0], b1 = bias[col0+1];
                *(float2*)(C + (size_t)row0*N + col0)     = make_float2(acc[i][j][0]+b0, acc[i][j][1]+b1);
                *(float2*)(C + (size_t)(row0+8)*N + col0) = make_float2(acc[i][j][2]+b0, acc[i][j][3]+b1);
            }
        }
    }
}

// ---------------- persistent recurrent layer: 16 units/block ----------------
// Block = 16 hidden units x 4 gates (64 cols) over 64 batch rows; grid = Kp/16
// blocks (72 big layers, 28 small); weights resident in smem fp16.
__global__ __launch_bounds__(256) void lstm_persist(
    const float* __restrict__ bh, const float* __restrict__ c0in,
    const float* __restrict__ xpre, __half* __restrict__ hs,
    int hstride, int D, int n4, int KT, int Kp)
{
    extern __shared__ uint32_t Wsm[];          // 64 rows x KS words
    __shared__ uint32_t Hsm[3][64*GSW];
    __shared__ float Gsm[64*65];
    __shared__ float c_sm[1024];

    int KS = (Kp >> 1) + 4;
    int tid = threadIdx.x, wid = tid >> 5, lane = tid & 31;
    int g = lane >> 2, tg = lane & 3;
    int wm = wid & 3, wn = wid >> 2;           // wm: batch quarter, wn: col half
    int u0 = blockIdx.x * 16;

    // weight slice: 64 rows (gate*16 + uu)
    int nq = Kp >> 3;
    for (int idx = tid; idx < 64*nq; idx += 256) {
        int r = idx / nq, q = idx - r*nq;
        int gate = r >> 4, uu = r & 15;
        uint4 v = *(const uint4*)(g_whp + ((size_t)(gate*DP + u0 + uu))*Kp + q*8);
        *(uint4*)((uint32_t*)Wsm + r*KS + q*4) = v;
    }
    for (int cell = tid; cell < 1024; cell += 256) {
        int b = cell >> 4, uu = cell & 15;
        int u = u0 + uu;
        c_sm[cell] = (u < D) ? c0in[b*D + u] : 0.f;
    }
    float bhv[4];
    {
        int uu = tid & 15, u = u0 + uu;
        #pragma unroll
        for (int gt = 0; gt < 4; ++gt)
            bhv[gt] = (u < D) ? bh[gt*D + u] : 0.f;
    }
    __syncthreads();

    int lr = tid >> 3, lq = tid & 7;

    for (int t = 0; t < T_; ++t) {
        const __half* hsrc = g_h[t & 1];
        __half*       hdst = g_h[(t & 1) ^ 1];
        const float* xp = xpre + (size_t)t * B_ * n4;

        float xg[4][4];
        #pragma unroll
        for (int cc = 0; cc < 4; ++cc) {
            int cell = tid + cc*256;
            int b = cell >> 4, uu = cell & 15;
            int u = u0 + uu;
            #pragma unroll
            for (int gt = 0; gt < 4; ++gt)
                xg[cc][gt] = (u < D) ? xp[(size_t)b*n4 + gt*D + u] : 0.f;
        }

        #pragma unroll
        for (int s = 0; s < 2; ++s) {
            if (s < KT) {
                int k0 = s*64;
                #pragma unroll
                for (int it = 0; it < 2; ++it) {
                    int r = lr + it*32;
                    cpa16(&Hsm[s][r*GSW + lq*4], hsrc + (size_t)r*DP + k0 + lq*8);
                }
            }
            cpcommit();
        }

        float acc[4][4];
        #pragma unroll
        for (int j = 0; j < 4; ++j)
            #pragma unroll
            for (int r = 0; r < 4; ++r) acc[j][r] = 0.f;

        for (int kc = 0; kc < KT; ++kc) {
            cpwait<1>();
            __syncthreads();
            {
                int kl = kc + 2;
                if (kl < KT) {
                    int s = kl % 3, k0 = kl*64;
                    #pragma unroll
                    for (int it = 0; it < 2; ++it) {
                        int r = lr + it*32;
                        cpa16(&Hsm[s][r*GSW + lq*4], hsrc + (size_t)r*DP + k0 + lq*8);
                    }
                }
                cpcommit();
            }
            const uint32_t* Hst = Hsm[kc % 3];
            int k0w = kc*32;
            #pragma unroll
            for (int ka = 0; ka < 4; ++ka) {
                int kw = ka*8 + tg;
                int mr = wm*16 + g;
                uint32_t a[4];
                a[0] = Hst[mr*GSW + kw];
                a[1] = Hst[(mr+8)*GSW + kw];
                a[2] = Hst[mr*GSW + kw + 4];
                a[3] = Hst[(mr+8)*GSW + kw + 4];
                #pragma unroll
                for (int j = 0; j < 4; ++j) {
                    int nc = wn*32 + j*8 + g;
                    uint32_t b[2];
                    b[0] = Wsm[nc*KS + k0w + kw];
                    b[1] = Wsm[nc*KS + k0w + kw + 4];
                    mma16(acc[j], a, b);
                }
            }
        }

        #pragma unroll
        for (int j = 0; j < 4; ++j) {
            int col = wn*32 + j*8 + tg*2;
            int row = wm*16 + g;
            Gsm[row*65 + col]       = acc[j][0];
            Gsm[row*65 + col + 1]   = acc[j][1];
            Gsm[(row+8)*65 + col]   = acc[j][2];
            Gsm[(row+8)*65 + col+1] = acc[j][3];
        }
        __syncthreads();

        #pragma unroll
        for (int cc = 0; cc < 4; ++cc) {
            int cell = tid + cc*256;
            int b = cell >> 4, uu = cell & 15;
            int u = u0 + uu;
            __half hval = __half(0.f);
            if (u < D) {
                float pf = Gsm[b*65 + uu]      + xg[cc][0] + bhv[0];
                float pi = Gsm[b*65 + 16 + uu] + xg[cc][1] + bhv[1];
                float po = Gsm[b*65 + 32 + uu] + xg[cc][2] + bhv[2];
                float pg = Gsm[b*65 + 48 + uu] + xg[cc][3] + bhv[3];
                float f = 1.f / (1.f + expf(-pf));
                float i = 1.f / (1.f + expf(-pi));
                float o = 1.f / (1.f + expf(-po));
                float gv = tanhf(pg);
                float c = f * c_sm[cell] + i * gv;
                c_sm[cell] = c;
                hval = __float2half_rn(o * tanhf(c));
                hs[((size_t)t * B_ + b) * hstride + u] = hval;
            }
            hdst[b*DP + u] = hval;
        }

        __threadfence();
        __syncthreads();
        if (tid == 0) {
            atomicAdd(&g_ctr, 1u);
            unsigned tgt = (unsigned)(t + 1) * gridDim.x;
            while (atomicAdd(&g_ctr, 0u) < tgt) {}
            __threadfence();
        }
        __syncthreads();
    }
}

// ---------------- host launcher --------------------------------------------
extern "C" void kernel_launch(void* const* d_in, const int* in_sizes, int n_in,
                              void* d_out, int out_size) {
    const int*   input = (const int*)  d_in[0];
    const float* h0 = (const float*)d_in[1],  *c0 = (const float*)d_in[2];
    const float* h1 = (const float*)d_in[3],  *c1 = (const float*)d_in[4];
    const float* h2 = (const float*)d_in[5],  *c2 = (const float*)d_in[6];
    const float* emb_w = (const float*)d_in[7];
    const float* wi0 = (const float*)d_in[8],  *bi0 = (const float*)d_in[9];
    const float* wh0 = (const float*)d_in[10], *bh0 = (const float*)d_in[11];
    const float* wi1 = (const float*)d_in[12], *bi1 = (const float*)d_in[13];
    const float* wh1 = (const float*)d_in[14], *bh1 = (const float*)d_in[15];
    const float* wi2 = (const float*)d_in[16], *bi2 = (const float*)d_in[17];
    const float* wh2 = (const float*)d_in[18], *bh2 = (const float*)d_in[19];
    const float* dec_b = (const float*)d_in[20];
    float* out = (float*)d_out;

    __half *x0, *hs0, *hs1, *hs2, *wip, *dec;
    float *xp0, *xp1, *xp2;
    cudaGetSymbolAddress((void**)&x0,  g_x0);
    cudaGetSymbolAddress((void**)&xp0, g_xpre0);
    cudaGetSymbolAddress((void**)&xp1, g_xpre1);
    cudaGetSymbolAddress((void**)&xp2, g_xpre2);
    cudaGetSymbolAddress((void**)&hs0, g_hs0);
    cudaGetSymbolAddress((void**)&hs1, g_hs1);
    cudaGetSymbolAddress((void**)&hs2, g_hs2);
    cudaGetSymbolAddress((void**)&wip, g_wip);
    cudaGetSymbolAddress((void**)&dec, g_dec);

    const int gemm_smem = 3*STG3*4;              // 98,304 B -> 2 CTAs/SM
    const int per_smem_big   = 64*((DP>>1)+4)*4;   // 148,480 B
    const int per_smem_small = 64*((KP0H>>1)+4)*4; //  58,368 B
    static int attr_done = 0;
    if (!attr_done) {
        cudaFuncSetAttribute(gemm_mma, cudaFuncAttributeMaxDynamicSharedMemorySize, gemm_smem);
        cudaFuncSetAttribute(lstm_persist, cudaFuncAttributeMaxDynamicSharedMemorySize, per_smem_big);
        attr_done = 1;
    }

    const int MB = M_ / 128;                  // 35

    // ================= layer 0 (persist is launch index 3 -> profiled) =====
    {
        int D = NHID_, N4 = 4*D;
        embed_packb0<<<M_ + PB0, 256>>>(input, emb_w, wi0);            // idx 0
        packwh_init0<<<PW0 + HCB, 256>>>(wh0, h0, D);                  // idx 1
        dim3 gg(36, MB);
        gemm_mma<<<gg, 128, gemm_smem>>>(x0, KP0H, wip, KP0H, bi0, xp0, N4, 7);  // idx 2
        lstm_persist<<<DP/16, 256, per_smem_big>>>(bh0, c0, xp0, hs0, DP, D, N4, 18, DP); // idx 3
    }
    // ================= layer 1: 1150 -> 1150 =================
    {
        int D = NHID_, N4 = 4*D;
        long tb4 = (long)4608*DP/4;
        pack_b<<<(int)((tb4+255)/256), 256>>>(wi1, wip, N4, NHID_, DP, tb4);
        dim3 gg(36, MB);
        gemm_mma<<<gg, 128, gemm_smem>>>(hs0, DP, wip, DP, bi1, xp1, N4, 18);
        long tw4 = (long)4*DP*DP/4;
        pack_wh<<<(int)((tw4+255)/256), 256>>>(wh1, D, DP, tw4);
        init_hc<<<HCB, 256>>>(h1, D);
        lstm_persist<<<DP/16, 256, per_smem_big>>>(bh1, c1, xp1, hs1, DP, D, N4, 18, DP);
    }
    // ================= layer 2: 1150 -> 400 =================
    {
        int D = NINP_, N4 = 4*D;
        long tb4 = (long)1664*DP/4;
        pack_b<<<(int)((tb4+255)/256), 256>>>(wi2, wip, N4, NHID_, DP, tb4);
        dim3 gg(13, MB);
        gemm_mma<<<gg, 128, gemm_smem>>>(hs1, DP, wip, DP, bi2, xp2, N4, 18);
        long tw4 = (long)4*DP*KP0H/4;
        pack_wh<<<(int)((tw4+255)/256), 256>>>(wh2, D, KP0H, tw4);
        init_hc<<<HCB, 256>>>(h2, D);
        lstm_persist<<<KP0H/16, 256, per_smem_small>>>(bh2, c2, xp2, hs2, KP0H, D, N4, 7, KP0H);
    }
    // ================= decoder =================
    {
        long tb4 = (long)DECROWS*KP0H/4;
        pack_b<<<(int)((tb4+255)/256), 256>>>(emb_w, dec, NTOK, NINP_, KP0H, tb4);
        dim3 gg(DECROWS/128, MB);
        gemm_mma<<<gg, 128, gemm_smem>>>(hs2, KP0H, dec, KP0H, dec_b, out, NTOK, 7);
    }
}

// round 14
// speedup vs baseline: 1.1222x; 1.1222x over previous
#include <cuda_runtime.h>
#include <cuda_fp16.h>
#include <math.h>
#include <stdint.h>

#define T_ 70
#define B_ 64
#define NTOK 33278
#define NINP_ 400
#define NHID_ 1150
#define DP 1152                 // padded hidden stride (halves)
#define KP0H 448                // padded 400-dim (halves)
#define M_ (T_*B_)              // 4480
#define GSW 36                  // persist smem row words (32 + 4 pad)
#define SRW 32                  // gemm swizzled row words
#define STG3 (2*128*SRW)        // gemm stage words (8192)
#define DECROWS 33536           // 262*128
#define PB0 2016                // pack_b layer0 blocks
#define PW0 5184                // pack_wh blocks
#define HCB 288                 // init blocks

// ---------------- static scratch ------------------------------------------
__device__ __half g_x0   [M_*KP0H];
__device__ float  g_xpre0[M_*4*NHID_];
__device__ float  g_xpre1[M_*4*NHID_];
__device__ float  g_xpre2[M_*4*NINP_];
__device__ __half g_hs0  [M_*DP];
__device__ __half g_hs1  [M_*DP];
__device__ __half g_hs2  [M_*KP0H];
__device__ __half g_h    [2][B_*DP];
__device__ __half g_whp  [4*DP*DP];
__device__ __half g_wip  [4608*DP];
__device__ __half g_dec  [DECROWS*KP0H];
__device__ unsigned int g_ctr;
__device__ unsigned int g_rel;

// ---------------- helpers -------------------------------------------------
__device__ __forceinline__ void mma16(float* c, const uint32_t* a, const uint32_t* b){
    asm volatile("mma.sync.aligned.m16n8k16.row.col.f32.f16.f16.f32 "
        "{%0,%1,%2,%3},{%4,%5,%6,%7},{%8,%9},{%0,%1,%2,%3};"
        : "+f"(c[0]),"+f"(c[1]),"+f"(c[2]),"+f"(c[3])
        : "r"(a[0]),"r"(a[1]),"r"(a[2]),"r"(a[3]),"r"(b[0]),"r"(b[1]));
}
__device__ __forceinline__ void cpa16(void* smem, const void* gmem){
    uint32_t s = (uint32_t)__cvta_generic_to_shared(smem);
    asm volatile("cp.async.cg.shared.global [%0], [%1], 16;" :: "r"(s), "l"(gmem));
}
__device__ __forceinline__ void cpcommit(){ asm volatile("cp.async.commit_group;"); }
template<int N> __device__ __forceinline__ void cpwait(){ asm volatile("cp.async.wait_group %0;" :: "n"(N)); }

// ---------------- fused: embed + pack_b (layer0) ----------------------------
__global__ void embed_packb0(const int* __restrict__ inp, const float* __restrict__ emb_w,
                             const float* __restrict__ wi0) {
    if (blockIdx.x < M_) {
        int token = blockIdx.x;
        int tok   = inp[token];
        const float* src = emb_w + (size_t)tok * NINP_;
        __half* dst = g_x0 + (size_t)token * KP0H;
        int j = threadIdx.x * 4;
        if (j < KP0H) {
            __half v[4];
            #pragma unroll
            for (int x = 0; x < 4; ++x) v[x] = (j + x < NINP_) ? __float2half_rn(src[j + x]) : __half(0.f);
            *(uint2*)(dst + j) = *(uint2*)v;
        }
    } else {
        long idx = (long)(blockIdx.x - M_) * 256 + threadIdx.x;
        long total4 = (long)4608 * KP0H / 4;
        if (idx >= total4) return;
        int kq = (int)(idx % (KP0H >> 2)) << 2;
        long n = idx / (KP0H >> 2);
        __half v[4];
        #pragma unroll
        for (int x = 0; x < 4; ++x)
            v[x] = (n < 4*NHID_ && kq + x < NINP_) ? __float2half_rn(wi0[n*NINP_ + kq + x]) : __half(0.f);
        *(uint2*)(g_wip + n*KP0H + kq) = *(uint2*)v;
    }
}

// ---------------- fused: pack_wh + init_hc (layer0) -------------------------
__global__ void packwh_init0(const float* __restrict__ wh, const float* __restrict__ h0, int D) {
    if (blockIdx.x < PW0) {
        long idx = (long)blockIdx.x * 256 + threadIdx.x;
        int kq = (int)(idx % (DP >> 2)) << 2;
        long r = idx / (DP >> 2);
        int u = (int)(r % DP);
        int gate = (int)(r / DP);
        __half v[4];
        #pragma unroll
        for (int x = 0; x < 4; ++x)
            v[x] = (u < D && kq + x < D) ? __float2half_rn(wh[((size_t)(gate*D + u))*D + kq + x]) : __half(0.f);
        *(uint2*)(g_whp + r*DP + kq) = *(uint2*)v;
    } else {
        int i = (blockIdx.x - PW0) * 256 + threadIdx.x;
        if (i == 0) { g_ctr = 0; g_rel = 0; }
        if (i >= B_*DP) return;
        int b = i / DP, u = i - b*DP;
        g_h[0][i] = (u < D) ? __float2half_rn(h0[b*D + u]) : __half(0.f);
    }
}

// ---------------- pack kernels (layers 1/2, decoder) ------------------------
__global__ void pack_b(const float* __restrict__ src, __half* __restrict__ dst,
                       int N, int K, int KP, long total4) {
    long idx = (long)blockIdx.x * 256 + threadIdx.x;
    if (idx >= total4) return;
    int kq = (int)(idx % (KP >> 2)) << 2;
    long n = idx / (KP >> 2);
    __half v[4];
    #pragma unroll
    for (int x = 0; x < 4; ++x)
        v[x] = (n < N && kq + x < K) ? __float2half_rn(src[n*K + kq + x]) : __half(0.f);
    *(uint2*)(dst + n*KP + kq) = *(uint2*)v;
}

__global__ void pack_wh(const float* __restrict__ wh, int D, int Kp, long total4) {
    long idx = (long)blockIdx.x * 256 + threadIdx.x;
    if (idx >= total4) return;
    int kq = (int)(idx % (Kp >> 2)) << 2;
    long r = idx / (Kp >> 2);
    int u = (int)(r % DP);
    int gate = (int)(r / DP);
    __half v[4];
    #pragma unroll
    for (int x = 0; x < 4; ++x)
        v[x] = (u < D && kq + x < D) ? __float2half_rn(wh[((size_t)(gate*D + u))*D + kq + x]) : __half(0.f);
    *(uint2*)(g_whp + r*Kp + kq) = *(uint2*)v;
}

__global__ void init_hc(const float* __restrict__ h0, int D) {
    int i = blockIdx.x * 256 + threadIdx.x;
    if (i == 0) { g_ctr = 0; g_rel = 0; }
    if (i >= B_*DP) return;
    int b = i / DP, u = i - b*DP;
    g_h[0][i] = (u < D) ? __float2half_rn(h0[b*D + u]) : __half(0.f);
}

// ---------------- fp16 GEMM (unchanged from R12) ----------------------------
__global__ __launch_bounds__(128, 2) void gemm_mma(
    const __half* __restrict__ A, int lda,
    const __half* __restrict__ B, int ldb,
    const float* __restrict__ bias, float* __restrict__ C,
    int N, int KT)
{
    extern __shared__ uint32_t sm[];
    int tid = threadIdx.x, wid = tid >> 5, lane = tid & 31;
    int g = lane >> 2, tg = lane & 3;
    int wm = wid >> 1, wn = wid & 1;
    int m0 = blockIdx.y * 128, n0 = blockIdx.x * 128;
    int r0 = tid >> 3, q = tid & 7;
    int swz = ((q ^ (r0 & 7)) << 2);

    float acc[4][8][4];
    #pragma unroll
    for (int i = 0; i < 4; ++i)
        #pragma unroll
        for (int j = 0; j < 8; ++j)
            #pragma unroll
            for (int r = 0; r < 4; ++r) acc[i][j][r] = 0.f;

    auto load_tile = [&](int s, int k0) {
        uint32_t* st = sm + s*STG3;
        const __half* ag = A + (size_t)(m0 + r0)*lda + k0 + q*8;
        #pragma unroll
        for (int it = 0; it < 8; ++it)
            cpa16(&st[(r0 + it*16)*SRW + swz], ag + (size_t)it*16*lda);
        uint32_t* sb = st + 128*SRW;
        const __half* bg = B + (size_t)(n0 + r0)*ldb + k0 + q*8;
        #pragma unroll
        for (int it = 0; it < 8; ++it)
            cpa16(&sb[(r0 + it*16)*SRW + swz], bg + (size_t)it*16*ldb);
    };

    load_tile(0, 0);  cpcommit();
    load_tile(1, 64); cpcommit();

    uint32_t a[2][4][4], b[2][8][2];

    for (int kt = 0; kt < KT; ++kt) {
        cpwait<1>();
        __syncthreads();
        if (kt + 2 < KT) load_tile((kt + 2) % 3, (kt + 2)*64);
        cpcommit();

        const uint32_t* Ast = sm + (kt % 3)*STG3;
        const uint32_t* Bst = Ast + 128*SRW;

        auto ldfrag = [&](int buf, int ka) {
            int aw0 = (((ka*2)     ^ g) << 2) + tg;
            int aw1 = (((ka*2 + 1) ^ g) << 2) + tg;
            #pragma unroll
            for (int i = 0; i < 4; ++i) {
                int mr = wm*64 + i*16 + g;
                a[buf][i][0] = Ast[mr*SRW + aw0];
                a[buf][i][1] = Ast[(mr+8)*SRW + aw0];
                a[buf][i][2] = Ast[mr*SRW + aw1];
                a[buf][i][3] = Ast[(mr+8)*SRW + aw1];
            }
            #pragma unroll
            for (int j = 0; j < 8; ++j) {
                int nc = wn*64 + j*8 + g;
                b[buf][j][0] = Bst[nc*SRW + aw0];
                b[buf][j][1] = Bst[nc*SRW + aw1];
            }
        };

        ldfrag(0, 0);
        #pragma unroll
        for (int ka = 0; ka < 4; ++ka) {
            int cur = ka & 1;
            if (ka < 3) ldfrag(cur ^ 1, ka + 1);
            #pragma unroll
            for (int i = 0; i < 4; ++i)
                #pragma unroll
                for (int j = 0; j < 8; ++j) mma16(acc[i][j], a[cur][i], b[cur][j]);
        }
    }

    #pragma unroll
    for (int i = 0; i < 4; ++i) {
        #pragma unroll
        for (int j = 0; j < 8; ++j) {
            int row0 = m0 + wm*64 + i*16 + g;
            int col0 = n0 + wn*64 + j*8 + tg*2;
            if (col0 < N) {
                float b0 = bias[col0], b1 = bias[col0+1];
                *(float2*)(C + (size_t)row0*N + col0)     = make_float2(acc[i][j][0]+b0, acc[i][j][1]+b1);
                *(float2*)(C + (size_t)(row0+8)*N + col0) = make_float2(acc[i][j][2]+b0, acc[i][j][3]+b1);
            }
        }
    }
}

// ---------------- persistent recurrent layer: 8 units/block -----------------
// R12 shape (144/52 blocks) + ka fragment double-buffering + release/acquire
// grid barrier (RMW arrive, read-only poll).
__global__ __launch_bounds__(256) void lstm_persist(
    const float* __restrict__ bh, const float* __restrict__ c0in,
    const float* __restrict__ xpre, __half* __restrict__ hs,
    int hstride, int D, int n4, int KT, int Kp)
{
    extern __shared__ uint32_t Wsm[];          // 32 rows x KS words
    __shared__ uint32_t Hsm[3][64*GSW];
    __shared__ float Gsm[64*33];
    __shared__ float c_sm[512];

    int KS = (Kp >> 1) + 4;
    int tid = threadIdx.x, wid = tid >> 5, lane = tid & 31;
    int g = lane >> 2, tg = lane & 3;
    int wm = wid & 3, wn = wid >> 2;
    int u0 = blockIdx.x * 8;

    int nq = Kp >> 3;
    for (int idx = tid; idx < 32*nq; idx += 256) {
        int r = idx / nq, q = idx - r*nq;
        int gate = r >> 3, uu = r & 7;
        uint4 v = *(const uint4*)(g_whp + ((size_t)(gate*DP + u0 + uu))*Kp + q*8);
        *(uint4*)((uint32_t*)Wsm + r*KS + q*4) = v;
    }
    for (int cell = tid; cell < 512; cell += 256) {
        int b = cell >> 3, uu = cell & 7;
        int u = u0 + uu;
        c_sm[cell] = (u < D) ? c0in[b*D + u] : 0.f;
    }
    float bhv[4];
    {
        int uu = tid & 7, u = u0 + uu;
        #pragma unroll
        for (int gt = 0; gt < 4; ++gt)
            bhv[gt] = (u < D) ? bh[gt*D + u] : 0.f;
    }
    __syncthreads();

    int lr = tid >> 3, lq = tid & 7;

    for (int t = 0; t < T_; ++t) {
        const __half* hsrc = g_h[t & 1];
        __half*       hdst = g_h[(t & 1) ^ 1];
        const float* xp = xpre + (size_t)t * B_ * n4;

        float xg[2][4];
        #pragma unroll
        for (int cc = 0; cc < 2; ++cc) {
            int cell = tid + cc*256;
            int b = cell >> 3, uu = cell & 7;
            int u = u0 + uu;
            #pragma unroll
            for (int gt = 0; gt < 4; ++gt)
                xg[cc][gt] = (u < D) ? xp[(size_t)b*n4 + gt*D + u] : 0.f;
        }

        #pragma unroll
        for (int s = 0; s < 2; ++s) {
            if (s < KT) {
                int k0 = s*64;
                #pragma unroll
                for (int it = 0; it < 2; ++it) {
                    int r = lr + it*32;
                    cpa16(&Hsm[s][r*GSW + lq*4], hsrc + (size_t)r*DP + k0 + lq*8);
                }
            }
            cpcommit();
        }

        float acc[2][4];
        #pragma unroll
        for (int j = 0; j < 2; ++j)
            #pragma unroll
            for (int r = 0; r < 4; ++r) acc[j][r] = 0.f;

        uint32_t a[2][4], b[2][2][2];

        for (int kc = 0; kc < KT; ++kc) {
            cpwait<1>();
            __syncthreads();
            {
                int kl = kc + 2;
                if (kl < KT) {
                    int s = kl % 3, k0 = kl*64;
                    #pragma unroll
                    for (int it = 0; it < 2; ++it) {
                        int r = lr + it*32;
                        cpa16(&Hsm[s][r*GSW + lq*4], hsrc + (size_t)r*DP + k0 + lq*8);
                    }
                }
                cpcommit();
            }
            const uint32_t* Hst = Hsm[kc % 3];
            int k0w = kc*32;

            auto ldfrag = [&](int buf, int ka) {
                int kw = ka*8 + tg;
                int mr = wm*16 + g;
                a[buf][0] = Hst[mr*GSW + kw];
                a[buf][1] = Hst[(mr+8)*GSW + kw];
                a[buf][2] = Hst[mr*GSW + kw + 4];
                a[buf][3] = Hst[(mr+8)*GSW + kw + 4];
                #pragma unroll
                for (int j = 0; j < 2; ++j) {
                    int nc = wn*16 + j*8 + g;
                    b[buf][j][0] = Wsm[nc*KS + k0w + kw];
                    b[buf][j][1] = Wsm[nc*KS + k0w + kw + 4];
                }
            };

            ldfrag(0, 0);
            #pragma unroll
            for (int ka = 0; ka < 4; ++ka) {
                int cur = ka & 1;
                if (ka < 3) ldfrag(cur ^ 1, ka + 1);
                mma16(acc[0], a[cur], b[cur][0]);
                mma16(acc[1], a[cur], b[cur][1]);
            }
        }

        #pragma unroll
        for (int j = 0; j < 2; ++j) {
            int col = wn*16 + j*8 + tg*2;
            int row = wm*16 + g;
            Gsm[row*33 + col]       = acc[j][0];
            Gsm[row*33 + col + 1]   = acc[j][1];
            Gsm[(row+8)*33 + col]   = acc[j][2];
            Gsm[(row+8)*33 + col+1] = acc[j][3];
        }
        __syncthreads();

        #pragma unroll
        for (int cc = 0; cc < 2; ++cc) {
            int cell = tid + cc*256;
            int b = cell >> 3, uu = cell & 7;
            int u = u0 + uu;
            __half hval = __half(0.f);
            if (u < D) {
                float pf = Gsm[b*33 + uu]      + xg[cc][0] + bhv[0];
                float pi = Gsm[b*33 + 8 + uu]  + xg[cc][1] + bhv[1];
                float po = Gsm[b*33 + 16 + uu] + xg[cc][2] + bhv[2];
                float pg = Gsm[b*33 + 24 + uu] + xg[cc][3] + bhv[3];
                float f = 1.f / (1.f + expf(-pf));
                float i = 1.f / (1.f + expf(-pi));
                float o = 1.f / (1.f + expf(-po));
                float gv = tanhf(pg);
                float c = f * c_sm[cell] + i * gv;
                c_sm[cell] = c;
                hval = __float2half_rn(o * tanhf(c));
                hs[((size_t)t * B_ + b) * hstride + u] = hval;
            }
            hdst[b*DP + u] = hval;
        }

        // release/acquire grid barrier: one RMW arrive per block, last block
        // publishes, everyone else polls with plain L2 reads
        __threadfence();
        __syncthreads();
        if (tid == 0) {
            unsigned old = atomicAdd(&g_ctr, 1u);
            if (old == (unsigned)(t + 1) * gridDim.x - 1u) {
                asm volatile("st.release.gpu.global.u32 [%0], %1;"
                             :: "l"(&g_rel), "r"((unsigned)(t + 1)) : "memory");
            }
            unsigned v;
            do {
                asm volatile("ld.acquire.gpu.global.u32 %0, [%1];" : "=r"(v) : "l"(&g_rel));
            } while (v < (unsigned)(t + 1));
        }
        __syncthreads();
    }
}

// ---------------- host launcher --------------------------------------------
extern "C" void kernel_launch(void* const* d_in, const int* in_sizes, int n_in,
                              void* d_out, int out_size) {
    const int*   input = (const int*)  d_in[0];
    const float* h0 = (const float*)d_in[1],  *c0 = (const float*)d_in[2];
    const float* h1 = (const float*)d_in[3],  *c1 = (const float*)d_in[4];
    const float* h2 = (const float*)d_in[5],  *c2 = (const float*)d_in[6];
    const float* emb_w = (const float*)d_in[7];
    const float* wi0 = (const float*)d_in[8],  *bi0 = (const float*)d_in[9];
    const float* wh0 = (const float*)d_in[10], *bh0 = (const float*)d_in[11];
    const float* wi1 = (const float*)d_in[12], *bi1 = (const float*)d_in[13];
    const float* wh1 = (const float*)d_in[14], *bh1 = (const float*)d_in[15];
    const float* wi2 = (const float*)d_in[16], *bi2 = (const float*)d_in[17];
    const float* wh2 = (const float*)d_in[18], *bh2 = (const float*)d_in[19];
    const float* dec_b = (const float*)d_in[20];
    float* out = (float*)d_out;

    __half *x0, *hs0, *hs1, *hs2, *wip, *dec;
    float *xp0, *xp1, *xp2;
    cudaGetSymbolAddress((void**)&x0,  g_x0);
    cudaGetSymbolAddress((void**)&xp0, g_xpre0);
    cudaGetSymbolAddress((void**)&xp1, g_xpre1);
    cudaGetSymbolAddress((void**)&xp2, g_xpre2);
    cudaGetSymbolAddress((void**)&hs0, g_hs0);
    cudaGetSymbolAddress((void**)&hs1, g_hs1);
    cudaGetSymbolAddress((void**)&hs2, g_hs2);
    cudaGetSymbolAddress((void**)&wip, g_wip);
    cudaGetSymbolAddress((void**)&dec, g_dec);

    const int gemm_smem = 3*STG3*4;                // 98,304 B -> 2 CTAs/SM
    const int per_smem_big   = 32*((DP>>1)+4)*4;   // 74,240 B
    const int per_smem_small = 32*((KP0H>>1)+4)*4; // 29,184 B
    static int attr_done = 0;
    if (!attr_done) {
        cudaFuncSetAttribute(gemm_mma, cudaFuncAttributeMaxDynamicSharedMemorySize, gemm_smem);
        cudaFuncSetAttribute(lstm_persist, cudaFuncAttributeMaxDynamicSharedMemorySize, per_smem_big);
        attr_done = 1;
    }

    const int MB = M_ / 128;                  // 35

    // ================= layer 0 (persist is launch index 3 -> profiled) =====
    {
        int D = NHID_, N4 = 4*D;
        embed_packb0<<<M_ + PB0, 256>>>(input, emb_w, wi0);            // idx 0
        packwh_init0<<<PW0 + HCB, 256>>>(wh0, h0, D);                  // idx 1
        dim3 gg(36, MB);
        gemm_mma<<<gg, 128, gemm_smem>>>(x0, KP0H, wip, KP0H, bi0, xp0, N4, 7);  // idx 2
        lstm_persist<<<144, 256, per_smem_big>>>(bh0, c0, xp0, hs0, DP, D, N4, 18, DP); // idx 3
    }
    // ================= layer 1: 1150 -> 1150 =================
    {
        int D = NHID_, N4 = 4*D;
        long tb4 = (long)4608*DP/4;
        pack_b<<<(int)((tb4+255)/256), 256>>>(wi1, wip, N4, NHID_, DP, tb4);
        dim3 gg(36, MB);
        gemm_mma<<<gg, 128, gemm_smem>>>(hs0, DP, wip, DP, bi1, xp1, N4, 18);
        long tw4 = (long)4*DP*DP/4;
        pack_wh<<<(int)((tw4+255)/256), 256>>>(wh1, D, DP, tw4);
        init_hc<<<HCB, 256>>>(h1, D);
        lstm_persist<<<144, 256, per_smem_big>>>(bh1, c1, xp1, hs1, DP, D, N4, 18, DP);
    }
    // ================= layer 2: 1150 -> 400 =================
    {
        int D = NINP_, N4 = 4*D;
        long tb4 = (long)1664*DP/4;
        pack_b<<<(int)((tb4+255)/256), 256>>>(wi2, wip, N4, NHID_, DP, tb4);
        dim3 gg(13, MB);
        gemm_mma<<<gg, 128, gemm_smem>>>(hs1, DP, wip, DP, bi2, xp2, N4, 18);
        long tw4 = (long)4*DP*KP0H/4;
        pack_wh<<<(int)((tw4+255)/256), 256>>>(wh2, D, KP0H, tw4);
        init_hc<<<HCB, 256>>>(h2, D);
        lstm_persist<<<KP0H/8, 256, per_smem_small>>>(bh2, c2, xp2, hs2, KP0H, D, N4, 7, KP0H);
    }
    // ================= decoder =================
    {
        long tb4 = (long)DECROWS*KP0H/4;
        pack_b<<<(int)((tb4+255)/256), 256>>>(emb_w, dec, NTOK, NINP_, KP0H, tb4);
        dim3 gg(DECROWS/128, MB);
        gemm_mma<<<gg, 128, gemm_smem>>>(hs2, KP0H, dec, KP0H, dec_b, out, NTOK, 7);
    }
}

// round 15
// speedup vs baseline: 1.2813x; 1.1417x over previous
#include <cuda_runtime.h>
#include <cuda_fp16.h>
#include <math.h>
#include <stdint.h>

#define T_ 70
#define B_ 64
#define NTOK 33278
#define NINP_ 400
#define NHID_ 1150
#define DP 1152                 // padded hidden stride (halves)
#define KP0H 448                // padded 400-dim (halves)
#define M_ (T_*B_)              // 4480
#define SRW 32                  // gemm swizzled row words
#define STG3 (2*128*SRW)        // gemm stage words (8192)
#define DECROWS 33536           // 262*128
#define PB0 2016                // pack_b layer0 blocks
#define PW0 5184                // pack_wh blocks
#define HCB 288                 // init blocks

// ---------------- static scratch ------------------------------------------
__device__ __half g_x0   [M_*KP0H];
__device__ float  g_xpre0[M_*4*NHID_];
__device__ float  g_xpre1[M_*4*NHID_];
__device__ float  g_xpre2[M_*4*NINP_];
__device__ __half g_hs0  [M_*DP];
__device__ __half g_hs1  [M_*DP];
__device__ __half g_hs2  [M_*KP0H];
__device__ __half g_h    [2][B_*DP];
__device__ __half g_whp  [4*DP*DP];
__device__ __half g_wip  [4608*DP];
__device__ __half g_dec  [DECROWS*KP0H];
__device__ unsigned int g_ctr;

// ---------------- helpers -------------------------------------------------
__device__ __forceinline__ void mma16(float* c, const uint32_t* a, const uint32_t* b){
    asm volatile("mma.sync.aligned.m16n8k16.row.col.f32.f16.f16.f32 "
        "{%0,%1,%2,%3},{%4,%5,%6,%7},{%8,%9},{%0,%1,%2,%3};"
        : "+f"(c[0]),"+f"(c[1]),"+f"(c[2]),"+f"(c[3])
        : "r"(a[0]),"r"(a[1]),"r"(a[2]),"r"(a[3]),"r"(b[0]),"r"(b[1]));
}
__device__ __forceinline__ void cpa16(void* smem, const void* gmem){
    uint32_t s = (uint32_t)__cvta_generic_to_shared(smem);
    asm volatile("cp.async.cg.shared.global [%0], [%1], 16;" :: "r"(s), "l"(gmem));
}
__device__ __forceinline__ void cpcommit(){ asm volatile("cp.async.commit_group;"); }
template<int N> __device__ __forceinline__ void cpwait(){ asm volatile("cp.async.wait_group %0;" :: "n"(N)); }

// ---------------- fused: embed + pack_b (layer0) ----------------------------
__global__ void embed_packb0(const int* __restrict__ inp, const float* __restrict__ emb_w,
                             const float* __restrict__ wi0) {
    if (blockIdx.x < M_) {
        int token = blockIdx.x;
        int tok   = inp[token];
        const float* src = emb_w + (size_t)tok * NINP_;
        __half* dst = g_x0 + (size_t)token * KP0H;
        int j = threadIdx.x * 4;
        if (j < KP0H) {
            __half v[4];
            #pragma unroll
            for (int x = 0; x < 4; ++x) v[x] = (j + x < NINP_) ? __float2half_rn(src[j + x]) : __half(0.f);
            *(uint2*)(dst + j) = *(uint2*)v;
        }
    } else {
        long idx = (long)(blockIdx.x - M_) * 256 + threadIdx.x;
        long total4 = (long)4608 * KP0H / 4;
        if (idx >= total4) return;
        int kq = (int)(idx % (KP0H >> 2)) << 2;
        long n = idx / (KP0H >> 2);
        __half v[4];
        #pragma unroll
        for (int x = 0; x < 4; ++x)
            v[x] = (n < 4*NHID_ && kq + x < NINP_) ? __float2half_rn(wi0[n*NINP_ + kq + x]) : __half(0.f);
        *(uint2*)(g_wip + n*KP0H + kq) = *(uint2*)v;
    }
}

// ---------------- fused: pack_wh + init_hc (layer0) -------------------------
__global__ void packwh_init0(const float* __restrict__ wh, const float* __restrict__ h0, int D) {
    if (blockIdx.x < PW0) {
        long idx = (long)blockIdx.x * 256 + threadIdx.x;
        int kq = (int)(idx % (DP >> 2)) << 2;
        long r = idx / (DP >> 2);
        int u = (int)(r % DP);
        int gate = (int)(r / DP);
        __half v[4];
        #pragma unroll
        for (int x = 0; x < 4; ++x)
            v[x] = (u < D && kq + x < D) ? __float2half_rn(wh[((size_t)(gate*D + u))*D + kq + x]) : __half(0.f);
        *(uint2*)(g_whp + r*DP + kq) = *(uint2*)v;
    } else {
        int i = (blockIdx.x - PW0) * 256 + threadIdx.x;
        if (i == 0) g_ctr = 0;
        if (i >= B_*DP) return;
        int b = i / DP, u = i - b*DP;
        g_h[0][i] = (u < D) ? __float2half_rn(h0[b*D + u]) : __half(0.f);
    }
}

// ---------------- pack kernels (layers 1/2, decoder) ------------------------
__global__ void pack_b(const float* __restrict__ src, __half* __restrict__ dst,
                       int N, int K, int KP, long total4) {
    long idx = (long)blockIdx.x * 256 + threadIdx.x;
    if (idx >= total4) return;
    int kq = (int)(idx % (KP >> 2)) << 2;
    long n = idx / (KP >> 2);
    __half v[4];
    #pragma unroll
    for (int x = 0; x < 4; ++x)
        v[x] = (n < N && kq + x < K) ? __float2half_rn(src[n*K + kq + x]) : __half(0.f);
    *(uint2*)(dst + n*KP + kq) = *(uint2*)v;
}

__global__ void pack_wh(const float* __restrict__ wh, int D, int Kp, long total4) {
    long idx = (long)blockIdx.x * 256 + threadIdx.x;
    if (idx >= total4) return;
    int kq = (int)(idx % (Kp >> 2)) << 2;
    long r = idx / (Kp >> 2);
    int u = (int)(r % DP);
    int gate = (int)(r / DP);
    __half v[4];
    #pragma unroll
    for (int x = 0; x < 4; ++x)
        v[x] = (u < D && kq + x < D) ? __float2half_rn(wh[((size_t)(gate*D + u))*D + kq + x]) : __half(0.f);
    *(uint2*)(g_whp + r*Kp + kq) = *(uint2*)v;
}

__global__ void init_hc(const float* __restrict__ h0, int D) {
    int i = blockIdx.x * 256 + threadIdx.x;
    if (i == 0) g_ctr = 0;
    if (i >= B_*DP) return;
    int b = i / DP, u = i - b*DP;
    g_h[0][i] = (u < D) ? __float2half_rn(h0[b*D + u]) : __half(0.f);
}

// ---------------- fp16 GEMM (R12-proven) ------------------------------------
__global__ __launch_bounds__(128, 2) void gemm_mma(
    const __half* __restrict__ A, int lda,
    const __half* __restrict__ B, int ldb,
    const float* __restrict__ bias, float* __restrict__ C,
    int N, int KT)
{
    extern __shared__ uint32_t sm[];
    int tid = threadIdx.x, wid = tid >> 5, lane = tid & 31;
    int g = lane >> 2, tg = lane & 3;
    int wm = wid >> 1, wn = wid & 1;
    int m0 = blockIdx.y * 128, n0 = blockIdx.x * 128;
    int r0 = tid >> 3, q = tid & 7;
    int swz = ((q ^ (r0 & 7)) << 2);

    float acc[4][8][4];
    #pragma unroll
    for (int i = 0; i < 4; ++i)
        #pragma unroll
        for (int j = 0; j < 8; ++j)
            #pragma unroll
            for (int r = 0; r < 4; ++r) acc[i][j][r] = 0.f;

    auto load_tile = [&](int s, int k0) {
        uint32_t* st = sm + s*STG3;
        const __half* ag = A + (size_t)(m0 + r0)*lda + k0 + q*8;
        #pragma unroll
        for (int it = 0; it < 8; ++it)
            cpa16(&st[(r0 + it*16)*SRW + swz], ag + (size_t)it*16*lda);
        uint32_t* sb = st + 128*SRW;
        const __half* bg = B + (size_t)(n0 + r0)*ldb + k0 + q*8;
        #pragma unroll
        for (int it = 0; it < 8; ++it)
            cpa16(&sb[(r0 + it*16)*SRW + swz], bg + (size_t)it*16*ldb);
    };

    load_tile(0, 0);  cpcommit();
    load_tile(1, 64); cpcommit();

    uint32_t a[2][4][4], b[2][8][2];

    for (int kt = 0; kt < KT; ++kt) {
        cpwait<1>();
        __syncthreads();
        if (kt + 2 < KT) load_tile((kt + 2) % 3, (kt + 2)*64);
        cpcommit();

        const uint32_t* Ast = sm + (kt % 3)*STG3;
        const uint32_t* Bst = Ast + 128*SRW;

        auto ldfrag = [&](int buf, int ka) {
            int aw0 = (((ka*2)     ^ g) << 2) + tg;
            int aw1 = (((ka*2 + 1) ^ g) << 2) + tg;
            #pragma unroll
            for (int i = 0; i < 4; ++i) {
                int mr = wm*64 + i*16 + g;
                a[buf][i][0] = Ast[mr*SRW + aw0];
                a[buf][i][1] = Ast[(mr+8)*SRW + aw0];
                a[buf][i][2] = Ast[mr*SRW + aw1];
                a[buf][i][3] = Ast[(mr+8)*SRW + aw1];
            }
            #pragma unroll
            for (int j = 0; j < 8; ++j) {
                int nc = wn*64 + j*8 + g;
                b[buf][j][0] = Bst[nc*SRW + aw0];
                b[buf][j][1] = Bst[nc*SRW + aw1];
            }
        };

        ldfrag(0, 0);
        #pragma unroll
        for (int ka = 0; ka < 4; ++ka) {
            int cur = ka & 1;
            if (ka < 3) ldfrag(cur ^ 1, ka + 1);
            #pragma unroll
            for (int i = 0; i < 4; ++i)
                #pragma unroll
                for (int j = 0; j < 8; ++j) mma16(acc[i][j], a[cur][i], b[cur][j]);
        }
    }

    #pragma unroll
    for (int i = 0; i < 4; ++i) {
        #pragma unroll
        for (int j = 0; j < 8; ++j) {
            int row0 = m0 + wm*64 + i*16 + g;
            int col0 = n0 + wn*64 + j*8 + tg*2;
            if (col0 < N) {
                float b0 = bias[col0], b1 = bias[col0+1];
                *(float2*)(C + (size_t)row0*N + col0)     = make_float2(acc[i][j][0]+b0, acc[i][j][1]+b1);
                *(float2*)(C + (size_t)(row0+8)*N + col0) = make_float2(acc[i][j][2]+b0, acc[i][j][3]+b1);
            }
        }
    }
}

// ---------------- persistent recurrent layer: monolithic h in smem ----------
// 8 units/block (144/56 blocks). Full h (64 x Kp) AND the 32-row W slice are
// resident in unpadded XOR-swizzled smem. Per step: one burst of cp.asyncs
// covering all of h, ONE cpwait, one sync, then KT sync-free compute chunks.
__global__ __launch_bounds__(256) void lstm_persist(
    const float* __restrict__ bh, const float* __restrict__ c0in,
    const float* __restrict__ xpre, __half* __restrict__ hs,
    int hstride, int D, int n4, int KT, int Kp)
{
    extern __shared__ uint32_t sm[];
    const int ROW = Kp >> 1;                    // words per row (no pad)
    uint32_t* Wsm = sm;                         // 32 rows
    uint32_t* Hsm = sm + 32*ROW;                // 64 rows
    __shared__ float Gsm[64*33];
    __shared__ float c_sm[512];

    int tid = threadIdx.x, wid = tid >> 5, lane = tid & 31;
    int g = lane >> 2, tg = lane & 3;
    int wm = wid & 3, wn = wid >> 2;
    int u0 = blockIdx.x * 8;

    // ---- load W slice once (swizzled) ----
    int nq = Kp >> 3;                           // 16B units per row
    for (int idx = tid; idx < 32*nq; idx += 256) {
        int r = idx / nq, q = idx - r*nq;
        int c = q >> 3, qq = q & 7;
        int gate = r >> 3, uu = r & 7;
        uint4 v = *(const uint4*)(g_whp + ((size_t)(gate*DP + u0 + uu))*Kp + q*8);
        *(uint4*)(Wsm + r*ROW + c*32 + ((qq ^ (r & 7)) << 2)) = v;
    }
    for (int cell = tid; cell < 512; cell += 256) {
        int b = cell >> 3, uu = cell & 7;
        int u = u0 + uu;
        c_sm[cell] = (u < D) ? c0in[b*D + u] : 0.f;
    }
    float bhv[4];
    {
        int uu = tid & 7, u = u0 + uu;
        #pragma unroll
        for (int gt = 0; gt < 4; ++gt)
            bhv[gt] = (u < D) ? bh[gt*D + u] : 0.f;
    }
    __syncthreads();

    int lr = tid >> 3, lq = tid & 7;            // h loader: 32 rows x 8 quads
    int swz0 = ((lq ^ (lr & 7)) << 2);
    int swz1 = ((lq ^ ((lr + 32) & 7)) << 2);

    for (int t = 0; t < T_; ++t) {
        const __half* hsrc = g_h[t & 1];
        __half*       hdst = g_h[(t & 1) ^ 1];
        const float* xp = xpre + (size_t)t * B_ * n4;

        // ---- one-shot h load: KT chunks x 2 row-groups, all in flight ----
        for (int c = 0; c < KT; ++c) {
            int k0 = c*64;
            cpa16(Hsm + lr*ROW + c*32 + swz0,        hsrc + (size_t)lr*DP + k0 + lq*8);
            cpa16(Hsm + (lr+32)*ROW + c*32 + swz1,   hsrc + (size_t)(lr+32)*DP + k0 + lq*8);
        }
        cpcommit();

        // xpre prefetch overlaps the h burst
        float xg[2][4];
        #pragma unroll
        for (int cc = 0; cc < 2; ++cc) {
            int cell = tid + cc*256;
            int b = cell >> 3, uu = cell & 7;
            int u = u0 + uu;
            #pragma unroll
            for (int gt = 0; gt < 4; ++gt)
                xg[cc][gt] = (u < D) ? xp[(size_t)b*n4 + gt*D + u] : 0.f;
        }

        cpwait<0>();
        __syncthreads();

        float acc[2][4];
        #pragma unroll
        for (int j = 0; j < 2; ++j)
            #pragma unroll
            for (int r = 0; r < 4; ++r) acc[j][r] = 0.f;

        int mr = wm*16 + g;
        int nc0 = wn*16 + g, nc1 = wn*16 + 8 + g;
        for (int kc = 0; kc < KT; ++kc) {
            int base = kc*32;
            #pragma unroll
            for (int ka = 0; ka < 4; ++ka) {
                int aw0 = (((ka*2)     ^ g) << 2) + tg;
                int aw1 = (((ka*2 + 1) ^ g) << 2) + tg;
                uint32_t a[4];
                a[0] = Hsm[mr*ROW + base + aw0];
                a[1] = Hsm[(mr+8)*ROW + base + aw0];
                a[2] = Hsm[mr*ROW + base + aw1];
                a[3] = Hsm[(mr+8)*ROW + base + aw1];
                uint32_t b0[2], b1[2];
                b0[0] = Wsm[nc0*ROW + base + aw0];
                b0[1] = Wsm[nc0*ROW + base + aw1];
                b1[0] = Wsm[nc1*ROW + base + aw0];
                b1[1] = Wsm[nc1*ROW + base + aw1];
                mma16(acc[0], a, b0);
                mma16(acc[1], a, b1);
            }
        }

        #pragma unroll
        for (int j = 0; j < 2; ++j) {
            int col = wn*16 + j*8 + tg*2;
            int row = wm*16 + g;
            Gsm[row*33 + col]       = acc[j][0];
            Gsm[row*33 + col + 1]   = acc[j][1];
            Gsm[(row+8)*33 + col]   = acc[j][2];
            Gsm[(row+8)*33 + col+1] = acc[j][3];
        }
        __syncthreads();

        #pragma unroll
        for (int cc = 0; cc < 2; ++cc) {
            int cell = tid + cc*256;
            int b = cell >> 3, uu = cell & 7;
            int u = u0 + uu;
            __half hval = __half(0.f);
            if (u < D) {
                float pf = Gsm[b*33 + uu]      + xg[cc][0] + bhv[0];
                float pi = Gsm[b*33 + 8 + uu]  + xg[cc][1] + bhv[1];
                float po = Gsm[b*33 + 16 + uu] + xg[cc][2] + bhv[2];
                float pg = Gsm[b*33 + 24 + uu] + xg[cc][3] + bhv[3];
                float f = 1.f / (1.f + expf(-pf));
                float i = 1.f / (1.f + expf(-pi));
                float o = 1.f / (1.f + expf(-po));
                float gv = tanhf(pg);
                float c = f * c_sm[cell] + i * gv;
                c_sm[cell] = c;
                hval = __float2half_rn(o * tanhf(c));
                hs[((size_t)t * B_ + b) * hstride + u] = hval;
            }
            hdst[b*DP + u] = hval;
        }

        __threadfence();
        __syncthreads();
        if (tid == 0) {
            atomicAdd(&g_ctr, 1u);
            unsigned tgt = (unsigned)(t + 1) * gridDim.x;
            while (atomicAdd(&g_ctr, 0u) < tgt) {}
            __threadfence();
        }
        __syncthreads();
    }
}

// ---------------- host launcher --------------------------------------------
extern "C" void kernel_launch(void* const* d_in, const int* in_sizes, int n_in,
                              void* d_out, int out_size) {
    const int*   input = (const int*)  d_in[0];
    const float* h0 = (const float*)d_in[1],  *c0 = (const float*)d_in[2];
    const float* h1 = (const float*)d_in[3],  *c1 = (const float*)d_in[4];
    const float* h2 = (const float*)d_in[5],  *c2 = (const float*)d_in[6];
    const float* emb_w = (const float*)d_in[7];
    const float* wi0 = (const float*)d_in[8],  *bi0 = (const float*)d_in[9];
    const float* wh0 = (const float*)d_in[10], *bh0 = (const float*)d_in[11];
    const float* wi1 = (const float*)d_in[12], *bi1 = (const float*)d_in[13];
    const float* wh1 = (const float*)d_in[14], *bh1 = (const float*)d_in[15];
    const float* wi2 = (const float*)d_in[16], *bi2 = (const float*)d_in[17];
    const float* wh2 = (const float*)d_in[18], *bh2 = (const float*)d_in[19];
    const float* dec_b = (const float*)d_in[20];
    float* out = (float*)d_out;

    __half *x0, *hs0, *hs1, *hs2, *wip, *dec;
    float *xp0, *xp1, *xp2;
    cudaGetSymbolAddress((void**)&x0,  g_x0);
    cudaGetSymbolAddress((void**)&xp0, g_xpre0);
    cudaGetSymbolAddress((void**)&xp1, g_xpre1);
    cudaGetSymbolAddress((void**)&xp2, g_xpre2);
    cudaGetSymbolAddress((void**)&hs0, g_hs0);
    cudaGetSymbolAddress((void**)&hs1, g_hs1);
    cudaGetSymbolAddress((void**)&hs2, g_hs2);
    cudaGetSymbolAddress((void**)&wip, g_wip);
    cudaGetSymbolAddress((void**)&dec, g_dec);

    const int gemm_smem = 3*STG3*4;                 // 98,304 B -> 2 CTAs/SM
    const int per_smem_big   = (32 + 64)*(DP>>1)*4;   // 221,184 B (W + full h)
    const int per_smem_small = (32 + 64)*(KP0H>>1)*4; //  86,016 B
    static int attr_done = 0;
    if (!attr_done) {
        cudaFuncSetAttribute(gemm_mma, cudaFuncAttributeMaxDynamicSharedMemorySize, gemm_smem);
        cudaFuncSetAttribute(lstm_persist, cudaFuncAttributeMaxDynamicSharedMemorySize, per_smem_big);
        attr_done = 1;
    }

    const int MB = M_ / 128;                  // 35

    // ================= layer 0 (persist is launch index 3 -> profiled) =====
    {
        int D = NHID_, N4 = 4*D;
        embed_packb0<<<M_ + PB0, 256>>>(input, emb_w, wi0);            // idx 0
        packwh_init0<<<PW0 + HCB, 256>>>(wh0, h0, D);                  // idx 1
        dim3 gg(36, MB);
        gemm_mma<<<gg, 128, gemm_smem>>>(x0, KP0H, wip, KP0H, bi0, xp0, N4, 7);  // idx 2
        lstm_persist<<<144, 256, per_smem_big>>>(bh0, c0, xp0, hs0, DP, D, N4, 18, DP); // idx 3
    }
    // ================= layer 1: 1150 -> 1150 =================
    {
        int D = NHID_, N4 = 4*D;
        long tb4 = (long)4608*DP/4;
        pack_b<<<(int)((tb4+255)/256), 256>>>(wi1, wip, N4, NHID_, DP, tb4);
        dim3 gg(36, MB);
        gemm_mma<<<gg, 128, gemm_smem>>>(hs0, DP, wip, DP, bi1, xp1, N4, 18);
        long tw4 = (long)4*DP*DP/4;
        pack_wh<<<(int)((tw4+255)/256), 256>>>(wh1, D, DP, tw4);
        init_hc<<<HCB, 256>>>(h1, D);
        lstm_persist<<<144, 256, per_smem_big>>>(bh1, c1, xp1, hs1, DP, D, N4, 18, DP);
    }
    // ================= layer 2: 1150 -> 400 =================
    {
        int D = NINP_, N4 = 4*D;
        long tb4 = (long)1664*DP/4;
        pack_b<<<(int)((tb4+255)/256), 256>>>(wi2, wip, N4, NHID_, DP, tb4);
        dim3 gg(13, MB);
        gemm_mma<<<gg, 128, gemm_smem>>>(hs1, DP, wip, DP, bi2, xp2, N4, 18);
        long tw4 = (long)4*DP*KP0H/4;
        pack_wh<<<(int)((tw4+255)/256), 256>>>(wh2, D, KP0H, tw4);
        init_hc<<<HCB, 256>>>(h2, D);
        lstm_persist<<<KP0H/8, 256, per_smem_small>>>(bh2, c2, xp2, hs2, KP0H, D, N4, 7, KP0H);
    }
    // ================= decoder =================
    {
        long tb4 = (long)DECROWS*KP0H/4;
        pack_b<<<(int)((tb4+255)/256), 256>>>(emb_w, dec, NTOK, NINP_, KP0H, tb4);
        dim3 gg(DECROWS/128, MB);
        gemm_mma<<<gg, 128, gemm_smem>>>(hs2, KP0H, dec, KP0H, dec_b, out, NTOK, 7);
    }
}

// round 16
// speedup vs baseline: 1.3820x; 1.0786x over previous
#include <cuda_runtime.h>
#include <cuda_fp16.h>
#include <math.h>
#include <stdint.h>

#define T_ 70
#define B_ 64
#define NTOK 33278
#define NINP_ 400
#define NHID_ 1150
#define DP 1152                 // padded hidden stride (halves)
#define KP0H 448                // padded 400-dim (halves)
#define M_ (T_*B_)              // 4480
#define SRW 32                  // gemm swizzled row words
#define STG3 (2*128*SRW)        // gemm stage words (8192)
#define DECROWS 33536           // 262*128
#define PB0 2016                // pack_b layer0 blocks
#define PW0 5184                // pack_wh blocks
#define HCB 288                 // init blocks

// ---------------- static scratch ------------------------------------------
__device__ __half g_x0   [M_*KP0H];
__device__ float  g_xpre0[M_*4*NHID_];
__device__ float  g_xpre1[M_*4*NHID_];
__device__ float  g_xpre2[M_*4*NINP_];
__device__ __half g_hs0  [M_*DP];
__device__ __half g_hs1  [M_*DP];
__device__ __half g_hs2  [M_*KP0H];
__device__ __half g_h    [2][B_*DP];
__device__ __half g_whp  [4*DP*DP];
__device__ __half g_wip  [4608*DP];
__device__ __half g_dec  [DECROWS*KP0H];
__device__ unsigned int g_ctr;

// ---------------- helpers -------------------------------------------------
__device__ __forceinline__ void mma16(float* c, const uint32_t* a, const uint32_t* b){
    asm volatile("mma.sync.aligned.m16n8k16.row.col.f32.f16.f16.f32 "
        "{%0,%1,%2,%3},{%4,%5,%6,%7},{%8,%9},{%0,%1,%2,%3};"
        : "+f"(c[0]),"+f"(c[1]),"+f"(c[2]),"+f"(c[3])
        : "r"(a[0]),"r"(a[1]),"r"(a[2]),"r"(a[3]),"r"(b[0]),"r"(b[1]));
}
__device__ __forceinline__ void cpa16(void* smem, const void* gmem){
    uint32_t s = (uint32_t)__cvta_generic_to_shared(smem);
    asm volatile("cp.async.cg.shared.global [%0], [%1], 16;" :: "r"(s), "l"(gmem));
}
__device__ __forceinline__ void cpcommit(){ asm volatile("cp.async.commit_group;"); }
template<int N> __device__ __forceinline__ void cpwait(){ asm volatile("cp.async.wait_group %0;" :: "n"(N)); }

// ---------------- fused: embed + pack_b (layer0) ----------------------------
__global__ void embed_packb0(const int* __restrict__ inp, const float* __restrict__ emb_w,
                             const float* __restrict__ wi0) {
    if (blockIdx.x < M_) {
        int token = blockIdx.x;
        int tok   = inp[token];
        const float* src = emb_w + (size_t)tok * NINP_;
        __half* dst = g_x0 + (size_t)token * KP0H;
        int j = threadIdx.x * 4;
        if (j < KP0H) {
            __half v[4];
            #pragma unroll
            for (int x = 0; x < 4; ++x) v[x] = (j + x < NINP_) ? __float2half_rn(src[j + x]) : __half(0.f);
            *(uint2*)(dst + j) = *(uint2*)v;
        }
    } else {
        long idx = (long)(blockIdx.x - M_) * 256 + threadIdx.x;
        long total4 = (long)4608 * KP0H / 4;
        if (idx >= total4) return;
        int kq = (int)(idx % (KP0H >> 2)) << 2;
        long n = idx / (KP0H >> 2);
        __half v[4];
        #pragma unroll
        for (int x = 0; x < 4; ++x)
            v[x] = (n < 4*NHID_ && kq + x < NINP_) ? __float2half_rn(wi0[n*NINP_ + kq + x]) : __half(0.f);
        *(uint2*)(g_wip + n*KP0H + kq) = *(uint2*)v;
    }
}

// ---------------- fused: pack_wh + init_hc (layer0) -------------------------
__global__ void packwh_init0(const float* __restrict__ wh, const float* __restrict__ h0, int D) {
    if (blockIdx.x < PW0) {
        long idx = (long)blockIdx.x * 256 + threadIdx.x;
        int kq = (int)(idx % (DP >> 2)) << 2;
        long r = idx / (DP >> 2);
        int u = (int)(r % DP);
        int gate = (int)(r / DP);
        __half v[4];
        #pragma unroll
        for (int x = 0; x < 4; ++x)
            v[x] = (u < D && kq + x < D) ? __float2half_rn(wh[((size_t)(gate*D + u))*D + kq + x]) : __half(0.f);
        *(uint2*)(g_whp + r*DP + kq) = *(uint2*)v;
    } else {
        int i = (blockIdx.x - PW0) * 256 + threadIdx.x;
        if (i == 0) g_ctr = 0;
        if (i >= B_*DP) return;
        int b = i / DP, u = i - b*DP;
        g_h[0][i] = (u < D) ? __float2half_rn(h0[b*D + u]) : __half(0.f);
    }
}

// ---------------- pack kernels (layers 1/2, decoder) ------------------------
__global__ void pack_b(const float* __restrict__ src, __half* __restrict__ dst,
                       int N, int K, int KP, long total4) {
    long idx = (long)blockIdx.x * 256 + threadIdx.x;
    if (idx >= total4) return;
    int kq = (int)(idx % (KP >> 2)) << 2;
    long n = idx / (KP >> 2);
    __half v[4];
    #pragma unroll
    for (int x = 0; x < 4; ++x)
        v[x] = (n < N && kq + x < K) ? __float2half_rn(src[n*K + kq + x]) : __half(0.f);
    *(uint2*)(dst + n*KP + kq) = *(uint2*)v;
}

__global__ void pack_wh(const float* __restrict__ wh, int D, int Kp, long total4) {
    long idx = (long)blockIdx.x * 256 + threadIdx.x;
    if (idx >= total4) return;
    int kq = (int)(idx % (Kp >> 2)) << 2;
    long r = idx / (Kp >> 2);
    int u = (int)(r % DP);
    int gate = (int)(r / DP);
    __half v[4];
    #pragma unroll
    for (int x = 0; x < 4; ++x)
        v[x] = (u < D && kq + x < D) ? __float2half_rn(wh[((size_t)(gate*D + u))*D + kq + x]) : __half(0.f);
    *(uint2*)(g_whp + r*Kp + kq) = *(uint2*)v;
}

__global__ void init_hc(const float* __restrict__ h0, int D) {
    int i = blockIdx.x * 256 + threadIdx.x;
    if (i == 0) g_ctr = 0;
    if (i >= B_*DP) return;
    int b = i / DP, u = i - b*DP;
    g_h[0][i] = (u < D) ? __float2half_rn(h0[b*D + u]) : __half(0.f);
}

// ---------------- fp16 GEMM ---------------------------------------------------
// Dd == 0: row-major C[M,N]. Dd > 0 (projection GEMMs, N = 4*Dd): write C in
// gate-interleaved layout C[m][u][gate] so the persist kernel reads float4.
__global__ __launch_bounds__(128, 2) void gemm_mma(
    const __half* __restrict__ A, int lda,
    const __half* __restrict__ B, int ldb,
    const float* __restrict__ bias, float* __restrict__ C,
    int N, int KT, int Dd)
{
    extern __shared__ uint32_t sm[];
    int tid = threadIdx.x, wid = tid >> 5, lane = tid & 31;
    int g = lane >> 2, tg = lane & 3;
    int wm = wid >> 1, wn = wid & 1;
    int m0 = blockIdx.y * 128, n0 = blockIdx.x * 128;
    int r0 = tid >> 3, q = tid & 7;
    int swz = ((q ^ (r0 & 7)) << 2);

    float acc[4][8][4];
    #pragma unroll
    for (int i = 0; i < 4; ++i)
        #pragma unroll
        for (int j = 0; j < 8; ++j)
            #pragma unroll
            for (int r = 0; r < 4; ++r) acc[i][j][r] = 0.f;

    auto load_tile = [&](int s, int k0) {
        uint32_t* st = sm + s*STG3;
        const __half* ag = A + (size_t)(m0 + r0)*lda + k0 + q*8;
        #pragma unroll
        for (int it = 0; it < 8; ++it)
            cpa16(&st[(r0 + it*16)*SRW + swz], ag + (size_t)it*16*lda);
        uint32_t* sb = st + 128*SRW;
        const __half* bg = B + (size_t)(n0 + r0)*ldb + k0 + q*8;
        #pragma unroll
        for (int it = 0; it < 8; ++it)
            cpa16(&sb[(r0 + it*16)*SRW + swz], bg + (size_t)it*16*ldb);
    };

    load_tile(0, 0);  cpcommit();
    load_tile(1, 64); cpcommit();

    uint32_t a[2][4][4], b[2][8][2];

    for (int kt = 0; kt < KT; ++kt) {
        cpwait<1>();
        __syncthreads();
        if (kt + 2 < KT) load_tile((kt + 2) % 3, (kt + 2)*64);
        cpcommit();

        const uint32_t* Ast = sm + (kt % 3)*STG3;
        const uint32_t* Bst = Ast + 128*SRW;

        auto ldfrag = [&](int buf, int ka) {
            int aw0 = (((ka*2)     ^ g) << 2) + tg;
            int aw1 = (((ka*2 + 1) ^ g) << 2) + tg;
            #pragma unroll
            for (int i = 0; i < 4; ++i) {
                int mr = wm*64 + i*16 + g;
                a[buf][i][0] = Ast[mr*SRW + aw0];
                a[buf][i][1] = Ast[(mr+8)*SRW + aw0];
                a[buf][i][2] = Ast[mr*SRW + aw1];
                a[buf][i][3] = Ast[(mr+8)*SRW + aw1];
            }
            #pragma unroll
            for (int j = 0; j < 8; ++j) {
                int nc = wn*64 + j*8 + g;
                b[buf][j][0] = Bst[nc*SRW + aw0];
                b[buf][j][1] = Bst[nc*SRW + aw1];
            }
        };

        ldfrag(0, 0);
        #pragma unroll
        for (int ka = 0; ka < 4; ++ka) {
            int cur = ka & 1;
            if (ka < 3) ldfrag(cur ^ 1, ka + 1);
            #pragma unroll
            for (int i = 0; i < 4; ++i)
                #pragma unroll
                for (int j = 0; j < 8; ++j) mma16(acc[i][j], a[cur][i], b[cur][j]);
        }
    }

    // epilogue
    #pragma unroll
    for (int i = 0; i < 4; ++i) {
        #pragma unroll
        for (int j = 0; j < 8; ++j) {
            int row0 = m0 + wm*64 + i*16 + g;
            int col0 = n0 + wn*64 + j*8 + tg*2;
            if (col0 < N) {
                if (Dd == 0) {
                    float b0 = bias[col0], b1 = bias[col0+1];
                    *(float2*)(C + (size_t)row0*N + col0)     = make_float2(acc[i][j][0]+b0, acc[i][j][1]+b1);
                    *(float2*)(C + (size_t)(row0+8)*N + col0) = make_float2(acc[i][j][2]+b0, acc[i][j][3]+b1);
                } else {
                    #pragma unroll
                    for (int e = 0; e < 2; ++e) {
                        int col = col0 + e;
                        int gate = col / Dd;
                        int u = col - gate * Dd;
                        float bv = bias[col];
                        C[((size_t)row0*Dd + u)*4 + gate]     = acc[i][j][e]   + bv;
                        C[((size_t)(row0+8)*Dd + u)*4 + gate] = acc[i][j][2+e] + bv;
                    }
                }
            }
        }
    }
}

// ---------------- persistent recurrent layer (templated, monolithic h) ------
// 8 units/block. Full h + W slice resident in unpadded XOR-swizzled smem.
// h loaded in 2 commit groups; first half computes while second is in flight.
// xpre is gate-interleaved: one float4 per (b, u).
template<int KT, int Kp>
__global__ __launch_bounds__(256) void lstm_persist(
    const float* __restrict__ bh, const float* __restrict__ c0in,
    const float* __restrict__ xpre, __half* __restrict__ hs,
    int hstride, int D)
{
    extern __shared__ uint32_t sm[];
    constexpr int ROW = Kp >> 1;
    constexpr int KH = KT / 2;
    uint32_t* Wsm = sm;                         // 32 rows
    uint32_t* Hsm = sm + 32*ROW;                // 64 rows
    __shared__ float Gsm[64*33];
    __shared__ float c_sm[512];

    int tid = threadIdx.x, wid = tid >> 5, lane = tid & 31;
    int g = lane >> 2, tg = lane & 3;
    int wm = wid & 3, wn = wid >> 2;
    int u0 = blockIdx.x * 8;

    // ---- load W slice once (swizzled) ----
    constexpr int nq = Kp >> 3;
    for (int idx = tid; idx < 32*nq; idx += 256) {
        int r = idx / nq, q = idx - r*nq;
        int c = q >> 3, qq = q & 7;
        int gate = r >> 3, uu = r & 7;
        uint4 v = *(const uint4*)(g_whp + ((size_t)(gate*DP + u0 + uu))*Kp + q*8);
        *(uint4*)(Wsm + r*ROW + c*32 + ((qq ^ (r & 7)) << 2)) = v;
    }
    for (int cell = tid; cell < 512; cell += 256) {
        int b = cell >> 3, uu = cell & 7;
        int u = u0 + uu;
        c_sm[cell] = (u < D) ? c0in[b*D + u] : 0.f;
    }
    float bhv[4];
    {
        int uu = tid & 7, u = u0 + uu;
        #pragma unroll
        for (int gt = 0; gt < 4; ++gt)
            bhv[gt] = (u < D) ? bh[gt*D + u] : 0.f;
    }
    __syncthreads();

    int lr = tid >> 3, lq = tid & 7;
    int swz0 = ((lq ^ (lr & 7)) << 2);
    int swz1 = ((lq ^ ((lr + 32) & 7)) << 2);
    int mr = wm*16 + g;
    int nc0 = wn*16 + g, nc1 = wn*16 + 8 + g;
    const uint32_t* Ha  = Hsm + mr*ROW;
    const uint32_t* Hb  = Hsm + (mr+8)*ROW;
    const uint32_t* W0  = Wsm + nc0*ROW;
    const uint32_t* W1  = Wsm + nc1*ROW;
    uint32_t* HL0 = Hsm + lr*ROW + swz0;
    uint32_t* HL1 = Hsm + (lr+32)*ROW + swz1;

    for (int t = 0; t < T_; ++t) {
        const __half* hsrc = g_h[t & 1];
        __half*       hdst = g_h[(t & 1) ^ 1];
        const __half* hs0 = hsrc + (size_t)lr*DP + lq*8;
        const __half* hs1 = hsrc + (size_t)(lr+32)*DP + lq*8;
        const float* xp = xpre + (size_t)t * B_ * 4 * D;

        // ---- h load in two commit groups ----
        #pragma unroll
        for (int c = 0; c < KH; ++c) {
            cpa16(HL0 + c*32, hs0 + c*64);
            cpa16(HL1 + c*32, hs1 + c*64);
        }
        cpcommit();
        #pragma unroll
        for (int c = KH; c < KT; ++c) {
            cpa16(HL0 + c*32, hs0 + c*64);
            cpa16(HL1 + c*32, hs1 + c*64);
        }
        cpcommit();

        // xpre prefetch: one float4 per cell (gate-interleaved layout)
        float xg[2][4];
        #pragma unroll
        for (int cc = 0; cc < 2; ++cc) {
            int cell = tid + cc*256;
            int b = cell >> 3, uu = cell & 7;
            int u = u0 + uu;
            if (u < D) {
                float4 v = *(const float4*)(xp + ((size_t)b*D + u)*4);
                xg[cc][0] = v.x; xg[cc][1] = v.y; xg[cc][2] = v.z; xg[cc][3] = v.w;
            } else {
                xg[cc][0] = xg[cc][1] = xg[cc][2] = xg[cc][3] = 0.f;
            }
        }

        float acc[2][4];
        #pragma unroll
        for (int j = 0; j < 2; ++j)
            #pragma unroll
            for (int r = 0; r < 4; ++r) acc[j][r] = 0.f;

        // ---- first half ----
        cpwait<1>();
        __syncthreads();
        #pragma unroll
        for (int kc = 0; kc < KH; ++kc) {
            #pragma unroll
            for (int ka = 0; ka < 4; ++ka) {
                int aw0 = kc*32 + (((ka*2)     ^ g) << 2) + tg;
                int aw1 = kc*32 + (((ka*2 + 1) ^ g) << 2) + tg;
                uint32_t a[4] = {Ha[aw0], Hb[aw0], Ha[aw1], Hb[aw1]};
                uint32_t b0[2] = {W0[aw0], W0[aw1]};
                uint32_t b1[2] = {W1[aw0], W1[aw1]};
                mma16(acc[0], a, b0);
                mma16(acc[1], a, b1);
            }
        }
        // ---- second half ----
        cpwait<0>();
        __syncthreads();
        #pragma unroll
        for (int kc = KH; kc < KT; ++kc) {
            #pragma unroll
            for (int ka = 0; ka < 4; ++ka) {
                int aw0 = kc*32 + (((ka*2)     ^ g) << 2) + tg;
                int aw1 = kc*32 + (((ka*2 + 1) ^ g) << 2) + tg;
                uint32_t a[4] = {Ha[aw0], Hb[aw0], Ha[aw1], Hb[aw1]};
                uint32_t b0[2] = {W0[aw0], W0[aw1]};
                uint32_t b1[2] = {W1[aw0], W1[aw1]};
                mma16(acc[0], a, b0);
                mma16(acc[1], a, b1);
            }
        }

        #pragma unroll
        for (int j = 0; j < 2; ++j) {
            int col = wn*16 + j*8 + tg*2;
            int row = wm*16 + g;
            Gsm[row*33 + col]       = acc[j][0];
            Gsm[row*33 + col + 1]   = acc[j][1];
            Gsm[(row+8)*33 + col]   = acc[j][2];
            Gsm[(row+8)*33 + col+1] = acc[j][3];
        }
        __syncthreads();

        #pragma unroll
        for (int cc = 0; cc < 2; ++cc) {
            int cell = tid + cc*256;
            int b = cell >> 3, uu = cell & 7;
            int u = u0 + uu;
            __half hval = __half(0.f);
            if (u < D) {
                float pf = Gsm[b*33 + uu]      + xg[cc][0] + bhv[0];
                float pi = Gsm[b*33 + 8 + uu]  + xg[cc][1] + bhv[1];
                float po = Gsm[b*33 + 16 + uu] + xg[cc][2] + bhv[2];
                float pg = Gsm[b*33 + 24 + uu] + xg[cc][3] + bhv[3];
                float f = 1.f / (1.f + expf(-pf));
                float i = 1.f / (1.f + expf(-pi));
                float o = 1.f / (1.f + expf(-po));
                float gv = tanhf(pg);
                float c = f * c_sm[cell] + i * gv;
                c_sm[cell] = c;
                hval = __float2half_rn(o * tanhf(c));
                hs[((size_t)t * B_ + b) * hstride + u] = hval;
            }
            hdst[b*DP + u] = hval;
        }

        __threadfence();
        __syncthreads();
        if (tid == 0) {
            atomicAdd(&g_ctr, 1u);
            unsigned tgt = (unsigned)(t + 1) * gridDim.x;
            while (atomicAdd(&g_ctr, 0u) < tgt) {}
            __threadfence();
        }
        __syncthreads();
    }
}

// ---------------- host launcher --------------------------------------------
extern "C" void kernel_launch(void* const* d_in, const int* in_sizes, int n_in,
                              void* d_out, int out_size) {
    const int*   input = (const int*)  d_in[0];
    const float* h0 = (const float*)d_in[1],  *c0 = (const float*)d_in[2];
    const float* h1 = (const float*)d_in[3],  *c1 = (const float*)d_in[4];
    const float* h2 = (const float*)d_in[5],  *c2 = (const float*)d_in[6];
    const float* emb_w = (const float*)d_in[7];
    const float* wi0 = (const float*)d_in[8],  *bi0 = (const float*)d_in[9];
    const float* wh0 = (const float*)d_in[10], *bh0 = (const float*)d_in[11];
    const float* wi1 = (const float*)d_in[12], *bi1 = (const float*)d_in[13];
    const float* wh1 = (const float*)d_in[14], *bh1 = (const float*)d_in[15];
    const float* wi2 = (const float*)d_in[16], *bi2 = (const float*)d_in[17];
    const float* wh2 = (const float*)d_in[18], *bh2 = (const float*)d_in[19];
    const float* dec_b = (const float*)d_in[20];
    float* out = (float*)d_out;

    __half *x0, *hs0, *hs1, *hs2, *wip, *dec;
    float *xp0, *xp1, *xp2;
    cudaGetSymbolAddress((void**)&x0,  g_x0);
    cudaGetSymbolAddress((void**)&xp0, g_xpre0);
    cudaGetSymbolAddress((void**)&xp1, g_xpre1);
    cudaGetSymbolAddress((void**)&xp2, g_xpre2);
    cudaGetSymbolAddress((void**)&hs0, g_hs0);
    cudaGetSymbolAddress((void**)&hs1, g_hs1);
    cudaGetSymbolAddress((void**)&hs2, g_hs2);
    cudaGetSymbolAddress((void**)&wip, g_wip);
    cudaGetSymbolAddress((void**)&dec, g_dec);

    const int gemm_smem = 3*STG3*4;                   // 98,304 B -> 2 CTAs/SM
    const int per_smem_big   = (32 + 64)*(DP>>1)*4;   // 221,184 B
    const int per_smem_small = (32 + 64)*(KP0H>>1)*4; //  86,016 B
    static int attr_done = 0;
    if (!attr_done) {
        cudaFuncSetAttribute(gemm_mma, cudaFuncAttributeMaxDynamicSharedMemorySize, gemm_smem);
        cudaFuncSetAttribute(lstm_persist<18, DP>, cudaFuncAttributeMaxDynamicSharedMemorySize, per_smem_big);
        cudaFuncSetAttribute(lstm_persist<7, KP0H>, cudaFuncAttributeMaxDynamicSharedMemorySize, per_smem_small);
        attr_done = 1;
    }

    const int MB = M_ / 128;                  // 35

    // ================= layer 0 (persist is launch index 3 -> profiled) =====
    {
        int D = NHID_, N4 = 4*D;
        embed_packb0<<<M_ + PB0, 256>>>(input, emb_w, wi0);            // idx 0
        packwh_init0<<<PW0 + HCB, 256>>>(wh0, h0, D);                  // idx 1
        dim3 gg(36, MB);
        gemm_mma<<<gg, 128, gemm_smem>>>(x0, KP0H, wip, KP0H, bi0, xp0, N4, 7, D);  // idx 2
        lstm_persist<18, DP><<<144, 256, per_smem_big>>>(bh0, c0, xp0, hs0, DP, D); // idx 3
    }
    // ================= layer 1: 1150 -> 1150 =================
    {
        int D = NHID_, N4 = 4*D;
        long tb4 = (long)4608*DP/4;
        pack_b<<<(int)((tb4+255)/256), 256>>>(wi1, wip, N4, NHID_, DP, tb4);
        dim3 gg(36, MB);
        gemm_mma<<<gg, 128, gemm_smem>>>(hs0, DP, wip, DP, bi1, xp1, N4, 18, D);
        long tw4 = (long)4*DP*DP/4;
        pack_wh<<<(int)((tw4+255)/256), 256>>>(wh1, D, DP, tw4);
        init_hc<<<HCB, 256>>>(h1, D);
        lstm_persist<18, DP><<<144, 256, per_smem_big>>>(bh1, c1, xp1, hs1, DP, D);
    }
    // ================= layer 2: 1150 -> 400 =================
    {
        int D = NINP_, N4 = 4*D;
        long tb4 = (long)1664*DP/4;
        pack_b<<<(int)((tb4+255)/256), 256>>>(wi2, wip, N4, NHID_, DP, tb4);
        dim3 gg(13, MB);
        gemm_mma<<<gg, 128, gemm_smem>>>(hs1, DP, wip, DP, bi2, xp2, N4, 18, D);
        long tw4 = (long)4*DP*KP0H/4;
        pack_wh<<<(int)((tw4+255)/256), 256>>>(wh2, D, KP0H, tw4);
        init_hc<<<HCB, 256>>>(h2, D);
        lstm_persist<7, KP0H><<<KP0H/8, 256, per_smem_small>>>(bh2, c2, xp2, hs2, KP0H, D);
    }
    // ================= decoder =================
    {
        long tb4 = (long)DECROWS*KP0H/4;
        pack_b<<<(int)((tb4+255)/256), 256>>>(emb_w, dec, NTOK, NINP_, KP0H, tb4);
        dim3 gg(DECROWS/128, MB);
        gemm_mma<<<gg, 128, gemm_smem>>>(hs2, KP0H, dec, KP0H, dec_b, out, NTOK, 7, 0);
    }
}